// round 4
// baseline (speedup 1.0000x reference)
#include <cuda_runtime.h>

// 2-layer LSTM (H=100, B=512, L=168) + fc head, 48-step autoregressive rollout.
// 128 CTAs x 4 batch elems; 800 threads = 2 k-halves x 400 gate rows.
// Thread (half, r) accumulates gate row r over k = half, half+2, ... (parity
// split) so both layers split evenly; partial sums reduced in the cell update.
//
// Weights pre-transposed into g_WT[k][r] (k-major, gate order i,f,g,o):
//   k 0..99   : W_hh0      (layer0 recurrent)
//   k 100..199: W_ih1      (layer1 input-from-h0)
//   k 200..299: W_hh1      (layer1 recurrent)
//   k 300..303: zero pad
// k-rows 0..127 resident in smem; rows 128..303 streamed from L2 each step
// (weights stay L2-resident; ptxas front-batches the unrolled LDGs, MLP~8).

#define HH        100
#define R4        400
#define SEQ       168
#define STEPS     48
#define NBC       4
#define NCTA      128
#define NTHREADS  800
#define NSMROWS   128
#define NROWS_TOT 304

__device__ float g_WT[NROWS_TOT * R4];
__device__ float g_b0[R4], g_b1[R4], g_wx0[R4];
__device__ float g_fc[HH + 1];

// ---------------------------------------------------------------- prep ----
__global__ void prep_kernel(const float* __restrict__ Wih0,
                            const float* __restrict__ Whh0,
                            const float* __restrict__ bih0,
                            const float* __restrict__ bhh0,
                            const float* __restrict__ Wih1,
                            const float* __restrict__ Whh1,
                            const float* __restrict__ bih1,
                            const float* __restrict__ bhh1,
                            const float* __restrict__ fcw,
                            const float* __restrict__ fcb)
{
    int i0 = blockIdx.x * blockDim.x + threadIdx.x;
    int stride = gridDim.x * blockDim.x;
    for (int idx = i0; idx < NROWS_TOT * R4; idx += stride) {
        int k = idx / R4, r = idx - k * R4;
        float v = 0.f;
        if      (k < 100) v = Whh0[r * HH + k];
        else if (k < 200) v = Wih1[r * HH + (k - 100)];
        else if (k < 300) v = Whh1[r * HH + (k - 200)];
        g_WT[idx] = v;
    }
    for (int r = i0; r < R4; r += stride) {
        g_b0[r]  = bih0[r] + bhh0[r];
        g_b1[r]  = bih1[r] + bhh1[r];
        g_wx0[r] = Wih0[r];           // IN == 1
    }
    if (i0 < HH)  g_fc[i0] = fcw[i0];
    if (i0 == HH) g_fc[HH] = fcb[0];
}

// ---------------------------------------------------------------- math ----
__device__ __forceinline__ float sigf(float v) {
    return 1.f / (1.f + __expf(-v));
}
__device__ __forceinline__ float tanhfast(float v) {
    // 2/(1+e^{-2v}) - 1 ; saturates correctly at +-1, rel err ~1e-6
    return __fdividef(2.f, 1.f + __expf(-2.f * v)) - 1.f;
}

// smem layout (floats)
#define SM_WT   0
#define SM_HIN  (NSMROWS * R4)                 // 204 float4 (h0|h1|pad)
#define SM_G    (SM_HIN + 204 * 4)             // 800 float4 partial gates
#define SM_C0   (SM_G + NTHREADS * 4)
#define SM_C1   (SM_C0 + HH * 4)
#define SM_FC   (SM_C1 + HH * 4)               // 104
#define SM_XT   (SM_FC + 104)
#define SM_Y    (SM_XT + 4)
#define SM_TOT  (SM_Y + 4)

__global__ void __launch_bounds__(NTHREADS, 1)
lstm_kernel(const float* __restrict__ x, float* __restrict__ out)
{
    extern __shared__ float sm[];
    float*  sWT   = sm + SM_WT;
    float4* sHin4 = (float4*)(sm + SM_HIN);
    float*  sHinF = sm + SM_HIN;
    float*  sGf   = sm + SM_G;
    float4* sG4   = (float4*)sGf;
    float*  sC0   = sm + SM_C0;
    float*  sC1   = sm + SM_C1;
    float*  sFC   = sm + SM_FC;
    float*  sXt   = sm + SM_XT;
    float*  sY    = sm + SM_Y;

    const int tid  = threadIdx.x;            // 0..799
    const int half = tid >= R4;              // k-parity this thread covers
    const int r    = tid - half * R4;        // gate row 0..399
    const int bb   = blockIdx.x * NBC;       // batch base

    // resident weights (coalesced), state zero, fc copy
    for (int i = tid; i < NSMROWS * R4; i += NTHREADS) sWT[i] = g_WT[i];
    for (int i = tid; i < 204 * 4; i += NTHREADS) sHinF[i] = 0.f;
    for (int i = tid; i < HH * 4;  i += NTHREADS) { sC0[i] = 0.f; sC1[i] = 0.f; }
    for (int i = tid; i < HH + 1;  i += NTHREADS) sFC[i] = g_fc[i];
    if (tid < NBC) sXt[tid] = x[(bb + tid) * SEQ];      // (s=0,t=0) input

    const float wx0 = g_wx0[r];
    const float b0r = g_b0[r];
    const float b1r = g_b1[r];
    const int   jb_b = (tid < R4) ? tid / HH : 0;        // cell-update map
    const int   jb_j = (tid < R4) ? tid - jb_b * HH : 0;

    // per-thread weight bases for the parity-split loops
    const float* wl0 = sWT + half * R4 + r;                    // k = half+2i
    const float* wl1 = sWT + (100 + half) * R4 + r;            // k = 100+half+2i
    const float* wls = g_WT + (NSMROWS + half) * R4 + r;       // streamed

    __syncthreads();

    for (int s = 0; s < STEPS; s++) {
        for (int t = 0; t < SEQ; t++) {
            // ================= layer 0 partial gates =================
            float a0, a1, a2, a3;
            if (!half) {
                float4 xv4 = *(const float4*)sXt;
                a0 = fmaf(wx0, xv4.x, b0r);
                a1 = fmaf(wx0, xv4.y, b0r);
                a2 = fmaf(wx0, xv4.z, b0r);
                a3 = fmaf(wx0, xv4.w, b0r);
            } else { a0 = a1 = a2 = a3 = 0.f; }
            #pragma unroll 10
            for (int i = 0; i < 50; i++) {               // k = half + 2i < 100
                float  w  = wl0[i * (2 * R4)];
                float4 h4 = sHin4[half + 2 * i];
                a0 = fmaf(w, h4.x, a0);
                a1 = fmaf(w, h4.y, a1);
                a2 = fmaf(w, h4.z, a2);
                a3 = fmaf(w, h4.w, a3);
            }
            sG4[tid] = make_float4(a0, a1, a2, a3);
            __syncthreads();

            // ---- layer 0 cell update (threads 0..399) ----
            if (tid < R4) {
                int o = jb_j * 4 + jb_b;
                float gi = sGf[o]             + sGf[(R4 + jb_j) * 4 + jb_b];
                float gf = sGf[(jb_j+100)*4+jb_b] + sGf[(R4+jb_j+100)*4+jb_b];
                float gg = sGf[(jb_j+200)*4+jb_b] + sGf[(R4+jb_j+200)*4+jb_b];
                float go = sGf[(jb_j+300)*4+jb_b] + sGf[(R4+jb_j+300)*4+jb_b];
                float c  = sC0[o];
                float cn = sigf(gf) * c + sigf(gi) * tanhfast(gg);
                float hn = sigf(go) * tanhfast(cn);
                sC0[o]   = cn;
                sHinF[o] = hn;                           // hin[0..99] = h0
            }
            __syncthreads();

            // ================= layer 1 partial gates =================
            a0 = half ? 0.f : b1r; a1 = a0; a2 = a0; a3 = a0;
            #pragma unroll
            for (int i = 0; i < 14; i++) {      // resident: k = 100+half+2i
                float  w  = wl1[i * (2 * R4)];
                float4 h4 = sHin4[half + 2 * i];
                a0 = fmaf(w, h4.x, a0);
                a1 = fmaf(w, h4.y, a1);
                a2 = fmaf(w, h4.z, a2);
                a3 = fmaf(w, h4.w, a3);
            }
            #pragma unroll 8
            for (int i = 0; i < 88; i++) {      // streamed: k = 128+half+2i
                float  w  = __ldg(wls + i * (2 * R4));
                float4 h4 = sHin4[28 + half + 2 * i];
                a0 = fmaf(w, h4.x, a0);
                a1 = fmaf(w, h4.y, a1);
                a2 = fmaf(w, h4.z, a2);
                a3 = fmaf(w, h4.w, a3);
            }
            sG4[tid] = make_float4(a0, a1, a2, a3);
            __syncthreads();

            // ---- layer 1 cell update + next-x prefetch ----
            if (tid < R4) {
                int o = jb_j * 4 + jb_b;
                float gi = sGf[o]             + sGf[(R4 + jb_j) * 4 + jb_b];
                float gf = sGf[(jb_j+100)*4+jb_b] + sGf[(R4+jb_j+100)*4+jb_b];
                float gg = sGf[(jb_j+200)*4+jb_b] + sGf[(R4+jb_j+200)*4+jb_b];
                float go = sGf[(jb_j+300)*4+jb_b] + sGf[(R4+jb_j+300)*4+jb_b];
                float c  = sC1[o];
                float cn = sigf(gf) * c + sigf(gi) * tanhfast(gg);
                float hn = sigf(go) * tanhfast(cn);
                sC1[o]              = cn;
                sHinF[(100+jb_j)*4 + jb_b] = hn;         // hin[100..199] = h1
            } else if (tid < R4 + NBC) {
                // prefetch input for the NEXT timestep (idle half-1 threads)
                int b  = tid - R4;
                int t2 = (t < SEQ - 1) ? t + 1 : 0;
                int s2 = (t < SEQ - 1) ? s : s + 1;
                if (s2 < STEPS) {
                    float xv;
                    if (s2 == 0)           xv = x[(bb + b) * SEQ + t2];
                    else if (t2 < SEQ - 1) xv = x[(bb + b) * SEQ + t2 + 1];
                    else                   xv = sY[b];   // y_{s2-1}, already final
                    sXt[b] = xv;
                }
            }
            __syncthreads();

            // ---- fc head at sequence end (overlaps next gate phase) ----
            if (t == SEQ - 1 && tid < 128) {
                int b = tid >> 5, l = tid & 31;
                float p = 0.f;
                for (int j = l; j < HH; j += 32)
                    p += sHinF[(100 + j) * 4 + b] * sFC[j];
                #pragma unroll
                for (int off = 16; off; off >>= 1)
                    p += __shfl_down_sync(0xffffffffu, p, off);
                if (l == 0) {
                    float y = p + sFC[HH];
                    sY[b] = y;                           // next reader is 167 steps away
                    out[(bb + b) * STEPS + s] = y;
                }
            }
        }
    }
}

// -------------------------------------------------------------- launch ----
extern "C" void kernel_launch(void* const* d_in, const int* in_sizes, int n_in,
                              void* d_out, int out_size)
{
    const float* x    = (const float*)d_in[0];
    const float* Wih0 = (const float*)d_in[1];
    const float* Whh0 = (const float*)d_in[2];
    const float* bih0 = (const float*)d_in[3];
    const float* bhh0 = (const float*)d_in[4];
    const float* Wih1 = (const float*)d_in[5];
    const float* Whh1 = (const float*)d_in[6];
    const float* bih1 = (const float*)d_in[7];
    const float* bhh1 = (const float*)d_in[8];
    const float* fcw  = (const float*)d_in[9];
    const float* fcb  = (const float*)d_in[10];
    float* out = (float*)d_out;

    cudaFuncSetAttribute(lstm_kernel,
                         cudaFuncAttributeMaxDynamicSharedMemorySize,
                         SM_TOT * (int)sizeof(float));

    prep_kernel<<<128, 256>>>(Wih0, Whh0, bih0, bhh0,
                              Wih1, Whh1, bih1, bhh1, fcw, fcb);
    lstm_kernel<<<NCTA, NTHREADS, SM_TOT * (int)sizeof(float)>>>(x, out);
}

// round 5
// speedup vs baseline: 1.6438x; 1.6438x over previous
#include <cuda_runtime.h>

// 2-layer LSTM (H=100, B=512, L=168) + fc head, 48-step autoregressive rollout.
// 128 CTAs x 4 batch elems; 400 threads, one thread per gate row r (order i,f,g,o).
// k-dimension processed in PAIRS via fma.rn.f32x2: lane0/lane1 of each 64-bit
// accumulator hold the partial sums for k=2kp / k=2kp+1; one lane-sum at the end.
//
// Weight pairs g_WP[kp][r] = (WT[2kp][r], WT[2kp+1][r]) with WT k-major:
//   k 0..99   : W_hh0    (layer0 recurrent)      -> kp 0..49
//   k 100..199: W_ih1    (layer1 from h0)        -> kp 50..99
//   k 200..299: W_hh1    (layer1 recurrent)      -> kp 100..149
// kp 0..63 resident in smem (204.8 KB); kp 64..149 streamed from L2 each step.
//
// h stored pair-transposed: hinT[jp][b][2] (8 floats per jp), so one LDS.128
// yields the (h_2jp, h_2jp+1) pairs for two batch elements.

#define HH        100
#define R4        400
#define SEQ       168
#define STEPS     48
#define NBC       4
#define NCTA      128
#define NTHREADS  400
#define NSMPAIRS  64          // weight k-pairs resident in smem
#define NPAIRS    150         // used pairs (k 0..299)

__device__ float2 g_WP[NPAIRS * R4];
__device__ float  g_b0[R4], g_b1[R4], g_wx0[R4];
__device__ float  g_fc[HH + 1];

// ---------------------------------------------------------------- prep ----
__device__ __forceinline__ float wt_val(int k, int r,
                                        const float* Whh0, const float* Wih1,
                                        const float* Whh1)
{
    if (k < 100)      return Whh0[r * HH + k];
    else if (k < 200) return Wih1[r * HH + (k - 100)];
    else if (k < 300) return Whh1[r * HH + (k - 200)];
    return 0.f;
}

__global__ void prep_kernel(const float* __restrict__ Wih0,
                            const float* __restrict__ Whh0,
                            const float* __restrict__ bih0,
                            const float* __restrict__ bhh0,
                            const float* __restrict__ Wih1,
                            const float* __restrict__ Whh1,
                            const float* __restrict__ bih1,
                            const float* __restrict__ bhh1,
                            const float* __restrict__ fcw,
                            const float* __restrict__ fcb)
{
    int i0 = blockIdx.x * blockDim.x + threadIdx.x;
    int stride = gridDim.x * blockDim.x;
    for (int idx = i0; idx < NPAIRS * R4; idx += stride) {
        int kp = idx / R4, r = idx - kp * R4;
        g_WP[idx] = make_float2(wt_val(2 * kp,     r, Whh0, Wih1, Whh1),
                                wt_val(2 * kp + 1, r, Whh0, Wih1, Whh1));
    }
    for (int r = i0; r < R4; r += stride) {
        g_b0[r]  = bih0[r] + bhh0[r];
        g_b1[r]  = bih1[r] + bhh1[r];
        g_wx0[r] = Wih0[r];           // IN == 1
    }
    if (i0 < HH)  g_fc[i0] = fcw[i0];
    if (i0 == HH) g_fc[HH] = fcb[0];
}

// ---------------------------------------------------------------- math ----
typedef unsigned long long u64;

__device__ __forceinline__ void ffma2(u64& acc, u64 w, u64 h) {
    asm("fma.rn.f32x2 %0, %1, %2, %0;" : "+l"(acc) : "l"(w), "l"(h));
}
__device__ __forceinline__ float hsum2(u64 v) {
    float lo, hi;
    asm("mov.b64 {%0, %1}, %2;" : "=f"(lo), "=f"(hi) : "l"(v));
    return lo + hi;
}
__device__ __forceinline__ float sigf(float v) {
    return 1.f / (1.f + __expf(-v));
}
__device__ __forceinline__ float tanhfast(float v) {
    return __fdividef(2.f, 1.f + __expf(-2.f * v)) - 1.f;
}

// smem layout (float offsets)
#define SM_WP   0                                  // 64 pairs * 400 * 2
#define SM_HT   (NSMPAIRS * R4 * 2)                // hinT: 100 jp * 8
#define SM_G    (SM_HT + 100 * 8)                  // gates [r][b]: 1600
#define SM_C0   (SM_G + R4 * 4)                    // 400
#define SM_C1   (SM_C0 + R4)                       // 400
#define SM_FC   (SM_C1 + R4)                       // 104
#define SM_XT   (SM_FC + 104)                      // 4 (16B aligned)
#define SM_Y    (SM_XT + 4)                        // 4
#define SM_TOT  (SM_Y + 4)

__global__ void __launch_bounds__(NTHREADS, 1)
lstm_kernel(const float* __restrict__ x, float* __restrict__ out)
{
    extern __shared__ float sm[];
    float2*     sWP  = (float2*)sm;                // [kp*400 + r]
    float*      sHf  = sm + SM_HT;                 // hinT scalar view
    ulonglong2* sHu  = (ulonglong2*)(sm + SM_HT);  // [2*jp + (b>>1)]
    float*      sGf  = sm + SM_G;
    float4*     sG4  = (float4*)sGf;
    float*      sC0  = sm + SM_C0;
    float*      sC1  = sm + SM_C1;
    float*      sFC  = sm + SM_FC;
    float*      sXt  = sm + SM_XT;
    float*      sY   = sm + SM_Y;

    const int tid = threadIdx.x;        // 0..399 = gate row r
    const int r   = tid;
    const int bb  = blockIdx.x * NBC;

    // resident weight pairs (coalesced float2 copies)
    {
        const float2* src = g_WP;
        for (int i = tid; i < NSMPAIRS * R4; i += NTHREADS) sWP[i] = src[i];
    }
    for (int i = tid; i < 100 * 8; i += NTHREADS) sHf[i] = 0.f;
    for (int i = tid; i < R4; i += NTHREADS) { sC0[i] = 0.f; sC1[i] = 0.f; }
    for (int i = tid; i < HH + 1; i += NTHREADS) sFC[i] = g_fc[i];
    if (tid < NBC) sXt[tid] = x[(bb + tid) * SEQ];

    const float wx0 = g_wx0[r];
    const float b0r = g_b0[r];
    const float b1r = g_b1[r];
    const int   jb_b = tid / HH;                 // cell-update mapping
    const int   jb_j = tid - jb_b * HH;
    const int   hoff = (jb_j >> 1) * 8 + jb_b * 2 + (jb_j & 1);
    const float2* wres1 = sWP + 50 * R4 + r;     // L1 resident base (kp=50)
    const float2* wstr  = g_WP + NSMPAIRS * R4 + r;  // L1 streamed base (kp=64)

    __syncthreads();

    for (int s = 0; s < STEPS; s++) {
        for (int t = 0; t < SEQ; t++) {
            // ================= layer 0 gates (kp 0..49, resident) ========
            u64 c0 = 0, c1 = 0, c2 = 0, c3 = 0;
            {
                const float2* w = sWP + r;
                #pragma unroll 5
                for (int kp = 0; kp < 50; kp++) {
                    u64 w2 = *(const u64*)(w + kp * R4);
                    ulonglong2 hA = sHu[2 * kp];       // pairs for b0,b1
                    ulonglong2 hB = sHu[2 * kp + 1];   // pairs for b2,b3
                    ffma2(c0, w2, hA.x);
                    ffma2(c1, w2, hA.y);
                    ffma2(c2, w2, hB.x);
                    ffma2(c3, w2, hB.y);
                }
            }
            {
                float4 xv4 = *(const float4*)sXt;
                float a0 = fmaf(wx0, xv4.x, b0r) + hsum2(c0);
                float a1 = fmaf(wx0, xv4.y, b0r) + hsum2(c1);
                float a2 = fmaf(wx0, xv4.z, b0r) + hsum2(c2);
                float a3 = fmaf(wx0, xv4.w, b0r) + hsum2(c3);
                sG4[r] = make_float4(a0, a1, a2, a3);
            }
            __syncthreads();

            // ---- layer 0 cell update + next-x prefetch ----
            {
                float gi = sGf[ jb_j        * 4 + jb_b];
                float gf = sGf[(jb_j + 100) * 4 + jb_b];
                float gg = sGf[(jb_j + 200) * 4 + jb_b];
                float go = sGf[(jb_j + 300) * 4 + jb_b];
                float c  = sC0[jb_j * 4 + jb_b];
                float cn = sigf(gf) * c + sigf(gi) * tanhfast(gg);
                float hn = sigf(go) * tanhfast(cn);
                sC0[jb_j * 4 + jb_b] = cn;
                sHf[hoff] = hn;                       // h0 -> hinT jp 0..49
            }
            if (tid < NBC) {
                // prefetch x for next timestep (safe: sY written >=167 steps ago)
                int t2 = (t < SEQ - 1) ? t + 1 : 0;
                int s2 = (t < SEQ - 1) ? s : s + 1;
                if (s2 < STEPS) {
                    float xv;
                    if (s2 == 0)           xv = x[(bb + tid) * SEQ + t2];
                    else if (t2 < SEQ - 1) xv = x[(bb + tid) * SEQ + t2 + 1];
                    else                   xv = sY[tid];
                    sXt[tid] = xv;   // L0 phase already consumed old value
                }
            }
            __syncthreads();

            // ================= layer 1 gates (kp 50..149) ================
            c0 = 0; c1 = 0; c2 = 0; c3 = 0;
            #pragma unroll
            for (int i = 0; i < NSMPAIRS - 50; i++) {   // resident kp 50..63
                u64 w2 = *(const u64*)(wres1 + i * R4);
                ulonglong2 hA = sHu[2 * i];
                ulonglong2 hB = sHu[2 * i + 1];
                ffma2(c0, w2, hA.x);
                ffma2(c1, w2, hA.y);
                ffma2(c2, w2, hB.x);
                ffma2(c3, w2, hB.y);
            }
            #pragma unroll 8
            for (int i = 0; i < NPAIRS - NSMPAIRS; i++) {   // streamed kp 64..149
                u64 w2 = __ldg((const u64*)(wstr + i * R4));
                int jp = (NSMPAIRS - 50) + i;
                ulonglong2 hA = sHu[2 * jp];
                ulonglong2 hB = sHu[2 * jp + 1];
                ffma2(c0, w2, hA.x);
                ffma2(c1, w2, hA.y);
                ffma2(c2, w2, hB.x);
                ffma2(c3, w2, hB.y);
            }
            sG4[r] = make_float4(b1r + hsum2(c0), b1r + hsum2(c1),
                                 b1r + hsum2(c2), b1r + hsum2(c3));
            __syncthreads();

            // ---- layer 1 cell update ----
            {
                float gi = sGf[ jb_j        * 4 + jb_b];
                float gf = sGf[(jb_j + 100) * 4 + jb_b];
                float gg = sGf[(jb_j + 200) * 4 + jb_b];
                float go = sGf[(jb_j + 300) * 4 + jb_b];
                float c  = sC1[jb_j * 4 + jb_b];
                float cn = sigf(gf) * c + sigf(gi) * tanhfast(gg);
                float hn = sigf(go) * tanhfast(cn);
                sC1[jb_j * 4 + jb_b] = cn;
                sHf[400 + hoff] = hn;                 // h1 -> hinT jp 50..99
            }
            __syncthreads();

            // ---- fc head at sequence end (overlaps next L0 phase) ----
            if (t == SEQ - 1 && tid < 128) {
                int b = tid >> 5, l = tid & 31;
                float p = 0.f;
                for (int j = l; j < HH; j += 32)
                    p += sHf[400 + (j >> 1) * 8 + b * 2 + (j & 1)] * sFC[j];
                #pragma unroll
                for (int off = 16; off; off >>= 1)
                    p += __shfl_down_sync(0xffffffffu, p, off);
                if (l == 0) {
                    float y = p + sFC[HH];
                    sY[b] = y;                         // next reader 167 steps away
                    out[(bb + b) * STEPS + s] = y;
                }
            }
        }
    }
}

// -------------------------------------------------------------- launch ----
extern "C" void kernel_launch(void* const* d_in, const int* in_sizes, int n_in,
                              void* d_out, int out_size)
{
    const float* x    = (const float*)d_in[0];
    const float* Wih0 = (const float*)d_in[1];
    const float* Whh0 = (const float*)d_in[2];
    const float* bih0 = (const float*)d_in[3];
    const float* bhh0 = (const float*)d_in[4];
    const float* Wih1 = (const float*)d_in[5];
    const float* Whh1 = (const float*)d_in[6];
    const float* bih1 = (const float*)d_in[7];
    const float* bhh1 = (const float*)d_in[8];
    const float* fcw  = (const float*)d_in[9];
    const float* fcb  = (const float*)d_in[10];
    float* out = (float*)d_out;

    cudaFuncSetAttribute(lstm_kernel,
                         cudaFuncAttributeMaxDynamicSharedMemorySize,
                         SM_TOT * (int)sizeof(float));

    prep_kernel<<<128, 256>>>(Wih0, Whh0, bih0, bhh0,
                              Wih1, Whh1, bih1, bhh1, fcw, fcb);
    lstm_kernel<<<NCTA, NTHREADS, SM_TOT * (int)sizeof(float)>>>(x, out);
}